// round 4
// baseline (speedup 1.0000x reference)
#include <cuda_runtime.h>
#include <math.h>
#include <stdint.h>

// Problem constants
#define MTOK  4096      // B*T tokens
#define DD    1024      // model dim
#define INNER 2048      // expanded dim
#define SST   64        // state dim
#define HIDD  4096      // expert hidden
#define NE    4         // experts
#define TT    2048      // seq len
#define NB    2         // batch

// ---------------- scratch (static device memory; no allocations) -------------
__device__ float g_h1 [(size_t)MTOK*DD];
__device__ float g_xz [(size_t)MTOK*2*INNER];
__device__ float g_xm [(size_t)MTOK*INNER];
__device__ float g_dt [(size_t)MTOK*SST];
__device__ float g_Bm [(size_t)MTOK*SST];
__device__ float g_Cm [(size_t)MTOK*SST];
__device__ float g_y  [(size_t)MTOK*SST];
__device__ float g_u  [(size_t)MTOK*INNER];
__device__ float g_x2 [(size_t)MTOK*DD];
__device__ float g_h2 [(size_t)MTOK*DD];
__device__ float g_hid[(size_t)MTOK*HIDD];
__device__ float g_wfull[(size_t)MTOK*NE];
__device__ int   g_idx[NE*MTOK];
__device__ float g_wl [NE*MTOK];
__device__ int   g_cnt[NE];

__device__ __forceinline__ float sigmoidf_(float v){ return 1.0f/(1.0f+expf(-v)); }

// ---------------- epilogue functors ------------------------------------------
struct EpBias {
    const float* bias; float* C; int ldc;
    __device__ __forceinline__ void store(int r,int c,float acc) const {
        C[(size_t)r*ldc + c] = acc + bias[c];
    }
};
struct EpBiasSig {
    const float* bias; float* C; int ldc;
    __device__ __forceinline__ void store(int r,int c,float acc) const {
        C[(size_t)r*ldc + c] = sigmoidf_(acc + bias[c]);
    }
};
struct EpGelu {          // exact gelu, writes compacted hid rows
    const float* bias; float* C; int ldc;
    __device__ __forceinline__ void store(int r,int c,float acc) const {
        float v = acc + bias[c];
        C[(size_t)r*ldc + c] = 0.5f*v*(1.0f + erff(v*0.70710678118654752f));
    }
};
struct EpS2I {           // + s2i_b + D*x_main, * sigmoid(gate)
    const float* bias; const float* Dp; const float* xm; const float* xz; float* C;
    __device__ __forceinline__ void store(int r,int c,float acc) const {
        float v = acc + bias[c];
        v = fmaf(Dp[c], xm[(size_t)r*INNER + c], v);
        v *= sigmoidf_(xz[(size_t)r*(2*INNER) + INNER + c]);
        C[(size_t)r*INNER + c] = v;
    }
};
struct EpOut {           // + out_b + residual x ; dual store (x2 and d_out)
    const float* bias; const float* resid; float* C; float* out;
    __device__ __forceinline__ void store(int r,int c,float acc) const {
        float v = acc + bias[c] + resid[(size_t)r*DD + c];
        C[(size_t)r*DD + c] = v;
        out[(size_t)r*DD + c] = v;
    }
};
struct EpMoE2 {          // scatter: out[tok] += w * (acc + b2)
    const float* bias; const int* idx; const float* wl; float* out;
    __device__ __forceinline__ void store(int r,int c,float acc) const {
        int t = idx[r];
        out[(size_t)t*DD + c] += wl[r]*(acc + bias[c]);
    }
};

// ---------------- generic 128x128x16 SGEMM, A row-major [M,K], B row-major [K,N]
template<class Ep>
__global__ void __launch_bounds__(256)
gemm128(const float* __restrict__ A, const float* __restrict__ B,
        int M, int N, int K,
        const int* __restrict__ mcnt,   // if non-null: device row count
        const int* __restrict__ ridx,   // if non-null: gather A rows
        Ep ep)
{
    constexpr int BM=128, BN=128, BK=16;
    int Mr = mcnt ? *mcnt : M;
    int rb = blockIdx.y*BM;
    if (rb >= Mr) return;
    int nb = blockIdx.x*BN;

    __shared__ float As[BK][BM];
    __shared__ float Bs[BK][BN];

    int tid = threadIdx.x;
    int tx = tid & 15, ty = tid >> 4;

    float acc[8][8];
    #pragma unroll
    for (int i=0;i<8;i++)
        #pragma unroll
        for (int j=0;j<8;j++) acc[i][j]=0.f;

    for (int k0=0; k0<K; k0+=BK) {
        // load A tile (BMxBK), transposed into As[k][m]
        #pragma unroll
        for (int i=0;i<2;i++) {
            int idv = tid*2 + i;            // 0..511
            int row = idv >> 2;             // 0..127
            int kq  = (idv & 3) * 4;        // 0,4,8,12
            float4 v = make_float4(0.f,0.f,0.f,0.f);
            int gr = rb + row;
            if (gr < Mr) {
                int ar = ridx ? ridx[gr] : gr;
                v = *reinterpret_cast<const float4*>(A + (size_t)ar*K + k0 + kq);
            }
            As[kq+0][row]=v.x; As[kq+1][row]=v.y; As[kq+2][row]=v.z; As[kq+3][row]=v.w;
        }
        // load B tile (BKxBN)
        #pragma unroll
        for (int i=0;i<2;i++) {
            int idv = tid*2 + i;
            int kr = idv >> 5;              // 0..15
            int nq = (idv & 31) * 4;        // 0..124
            float4 v = make_float4(0.f,0.f,0.f,0.f);
            if (nb + nq < N)
                v = *reinterpret_cast<const float4*>(B + (size_t)(k0+kr)*N + nb + nq);
            *reinterpret_cast<float4*>(&Bs[kr][nq]) = v;
        }
        __syncthreads();

        #pragma unroll
        for (int k=0;k<BK;k++) {
            float a[8], b[8];
            *reinterpret_cast<float4*>(&a[0]) = *reinterpret_cast<float4*>(&As[k][ty*8]);
            *reinterpret_cast<float4*>(&a[4]) = *reinterpret_cast<float4*>(&As[k][ty*8+4]);
            *reinterpret_cast<float4*>(&b[0]) = *reinterpret_cast<float4*>(&Bs[k][tx*8]);
            *reinterpret_cast<float4*>(&b[4]) = *reinterpret_cast<float4*>(&Bs[k][tx*8+4]);
            #pragma unroll
            for (int i=0;i<8;i++)
                #pragma unroll
                for (int j=0;j<8;j++) acc[i][j] = fmaf(a[i], b[j], acc[i][j]);
        }
        __syncthreads();
    }

    #pragma unroll
    for (int i=0;i<8;i++) {
        int r = rb + ty*8 + i;
        if (r >= Mr) continue;
        #pragma unroll
        for (int j=0;j<8;j++) {
            int c = nb + tx*8 + j;
            if (c < N) ep.store(r, c, acc[i][j]);
        }
    }
}

// ---------------- rmsnorm (row of 1024), eps 1e-6 ----------------------------
__global__ void rmsnorm_kernel(const float* __restrict__ x, const float* __restrict__ w,
                               float* __restrict__ o)
{
    int r = blockIdx.x;
    const float* xr = x + (size_t)r*DD;
    float s = 0.f;
    for (int i=threadIdx.x; i<DD; i+=blockDim.x) { float v = xr[i]; s = fmaf(v,v,s); }
    #pragma unroll
    for (int off=16; off; off>>=1) s += __shfl_xor_sync(0xffffffffu, s, off);
    __shared__ float red[8];
    int wid = threadIdx.x>>5, lane = threadIdx.x&31;
    if (lane==0) red[wid]=s;
    __syncthreads();
    if (threadIdx.x==0) {
        float t=0.f;
        for (int i=0;i<(int)(blockDim.x>>5);i++) t += red[i];
        red[0] = rsqrtf(t/(float)DD + 1e-6f);
    }
    __syncthreads();
    float nr = red[0];
    float* orow = o + (size_t)r*DD;
    for (int i=threadIdx.x; i<DD; i+=blockDim.x) orow[i] = xr[i]*nr*w[i];
}

// ---------------- causal depthwise conv (K=3) + silu -------------------------
__global__ void conv_silu_kernel(const float* __restrict__ xz, const float* __restrict__ cw,
                                 const float* __restrict__ cb, float* __restrict__ xm)
{
    int idx = blockIdx.x*blockDim.x + threadIdx.x;       // over MTOK*INNER
    if (idx >= MTOK*INNER) return;
    int c   = idx & (INNER-1);
    int tok = idx >> 11;                                  // INNER = 2048
    int t   = tok & (TT-1);
    const float* base = xz + (size_t)tok*(2*INNER) + c;   // x_main half
    float v = cw[c*3+2]*base[0];
    if (t >= 1) v = fmaf(cw[c*3+1], base[-(ptrdiff_t)(2*INNER)],   v);
    if (t >= 2) v = fmaf(cw[c*3+0], base[-(ptrdiff_t)(4*INNER)],   v);
    v += cb[c];
    xm[idx] = v * sigmoidf_(v);
}

// ---------------- selective-state scan (serial over T) -----------------------
__global__ void scan_kernel(const float* __restrict__ dt, const float* __restrict__ Bv,
                            const float* __restrict__ Cv, float* __restrict__ y)
{
    int tid = threadIdx.x;          // 128 = NB * SST
    if (tid >= NB*SST) return;
    int b = tid >> 6, s = tid & 63;
    float st = 0.f;
    size_t off = ((size_t)b*TT)*SST + s;
    for (int t=0; t<TT; t++, off += SST) {
        float d = dt[off], bb = Bv[off], cc = Cv[off];
        st = fmaf(d, bb - st, st);           // (1-d)*st + d*b
        y[off] = cc*st;
    }
}

// ---------------- layernorm over 64 (one warp per token), eps 1e-5 -----------
__global__ void ln64_kernel(float* __restrict__ y)
{
    int gw = (blockIdx.x*blockDim.x + threadIdx.x) >> 5;
    if (gw >= MTOK) return;
    int lane = threadIdx.x & 31;
    float* r = y + (size_t)gw*SST;
    float v0 = r[lane], v1 = r[lane+32];
    float sum = v0 + v1;
    #pragma unroll
    for (int off=16; off; off>>=1) sum += __shfl_xor_sync(0xffffffffu, sum, off);
    float mu = sum * (1.0f/64.0f);
    float d0 = v0-mu, d1 = v1-mu;
    float vs = d0*d0 + d1*d1;
    #pragma unroll
    for (int off=16; off; off>>=1) vs += __shfl_xor_sync(0xffffffffu, vs, off);
    float nr = rsqrtf(vs*(1.0f/64.0f) + 1e-5f);
    r[lane]    = d0*nr;
    r[lane+32] = d1*nr;
}

// ---------------- gating: logits, top-2 softmax → dense weights --------------
__global__ void gate_kernel(const float* __restrict__ h2, const float* __restrict__ gw,
                            const float* __restrict__ gb, float* __restrict__ wfull)
{
    int gwarp = (blockIdx.x*blockDim.x + threadIdx.x) >> 5;
    if (gwarp >= MTOK) return;
    int lane = threadIdx.x & 31;
    float a0=0,a1=0,a2=0,a3=0;
    const float* hr = h2 + (size_t)gwarp*DD;
    for (int d=lane; d<DD; d+=32) {
        float h = hr[d];
        float4 w = *reinterpret_cast<const float4*>(gw + d*4);
        a0 = fmaf(h,w.x,a0); a1 = fmaf(h,w.y,a1);
        a2 = fmaf(h,w.z,a2); a3 = fmaf(h,w.w,a3);
    }
    #pragma unroll
    for (int off=16; off; off>>=1) {
        a0 += __shfl_xor_sync(0xffffffffu,a0,off);
        a1 += __shfl_xor_sync(0xffffffffu,a1,off);
        a2 += __shfl_xor_sync(0xffffffffu,a2,off);
        a3 += __shfl_xor_sync(0xffffffffu,a3,off);
    }
    if (lane==0) {
        float l[4] = {a0+gb[0], a1+gb[1], a2+gb[2], a3+gb[3]};
        int i0 = 0;
        for (int e=1;e<4;e++) if (l[e] > l[i0]) i0 = e;       // strict: earliest on tie
        int i1 = -1;
        for (int e=0;e<4;e++) if (e!=i0 && (i1<0 || l[e] > l[i1])) i1 = e;
        float e1 = expf(l[i1]-l[i0]);
        float p0 = 1.0f/(1.0f+e1);
        float p1 = e1/(1.0f+e1);
        float* wr = wfull + (size_t)gwarp*NE;
        wr[0]=0.f; wr[1]=0.f; wr[2]=0.f; wr[3]=0.f;
        wr[i0]=p0; wr[i1]=p1;
    }
}

// ---------------- deterministic per-expert token lists -----------------------
__global__ void build_lists_kernel(const float* __restrict__ wfull,
                                   int* __restrict__ idx, float* __restrict__ wl,
                                   int* __restrict__ cnt)
{
    int e = blockIdx.x;
    __shared__ int pref[1024];
    __shared__ int base;
    if (threadIdx.x==0) base = 0;
    __syncthreads();
    for (int chunk=0; chunk<MTOK/1024; chunk++) {
        int t = chunk*1024 + threadIdx.x;
        float w = wfull[(size_t)t*NE + e];
        int pred = (w > 0.f) ? 1 : 0;
        pref[threadIdx.x] = pred;
        __syncthreads();
        for (int off=1; off<1024; off<<=1) {
            int v = (threadIdx.x >= off) ? pref[threadIdx.x-off] : 0;
            __syncthreads();
            pref[threadIdx.x] += v;
            __syncthreads();
        }
        if (pred) {
            int pos = base + pref[threadIdx.x] - 1;
            idx[e*MTOK + pos] = t;
            wl [e*MTOK + pos] = w;
        }
        __syncthreads();
        if (threadIdx.x==0) base += pref[1023];
        __syncthreads();
    }
    if (threadIdx.x==0) cnt[e] = base;
}

// =============================================================================
extern "C" void kernel_launch(void* const* d_in, const int* in_sizes, int n_in,
                              void* d_out, int out_size)
{
    const float* x    = (const float*)d_in[0];
    const float* n1w  = (const float*)d_in[1];
    const float* n2w  = (const float*)d_in[2];
    const float* ipw  = (const float*)d_in[3];
    const float* ipb  = (const float*)d_in[4];
    const float* cw   = (const float*)d_in[5];
    const float* cb   = (const float*)d_in[6];
    const float* dtw  = (const float*)d_in[7];
    const float* dtb  = (const float*)d_in[8];
    const float* bpw  = (const float*)d_in[9];
    const float* bpb  = (const float*)d_in[10];
    const float* cpw  = (const float*)d_in[11];
    const float* cpb  = (const float*)d_in[12];
    const float* s2iw = (const float*)d_in[13];
    const float* s2ib = (const float*)d_in[14];
    const float* Dp   = (const float*)d_in[15];
    const float* ow   = (const float*)d_in[16];
    const float* obp  = (const float*)d_in[17];
    const float* gw   = (const float*)d_in[18];
    const float* gb   = (const float*)d_in[19];
    const float* ew1  = (const float*)d_in[20];
    const float* eb1  = (const float*)d_in[21];
    const float* ew2  = (const float*)d_in[22];
    const float* eb2  = (const float*)d_in[23];
    float* out = (float*)d_out;

    float *h1,*xz,*xm,*dt,*Bm,*Cm,*y,*u,*x2,*h2,*hid,*wfull,*wl;
    int *idx,*cnt;
    cudaGetSymbolAddress((void**)&h1,   g_h1);
    cudaGetSymbolAddress((void**)&xz,   g_xz);
    cudaGetSymbolAddress((void**)&xm,   g_xm);
    cudaGetSymbolAddress((void**)&dt,   g_dt);
    cudaGetSymbolAddress((void**)&Bm,   g_Bm);
    cudaGetSymbolAddress((void**)&Cm,   g_Cm);
    cudaGetSymbolAddress((void**)&y,    g_y);
    cudaGetSymbolAddress((void**)&u,    g_u);
    cudaGetSymbolAddress((void**)&x2,   g_x2);
    cudaGetSymbolAddress((void**)&h2,   g_h2);
    cudaGetSymbolAddress((void**)&hid,  g_hid);
    cudaGetSymbolAddress((void**)&wfull,g_wfull);
    cudaGetSymbolAddress((void**)&wl,   g_wl);
    cudaGetSymbolAddress((void**)&idx,  g_idx);
    cudaGetSymbolAddress((void**)&cnt,  g_cnt);

    // ---- mixer ----
    rmsnorm_kernel<<<MTOK, 256>>>(x, n1w, h1);

    gemm128<EpBias><<<dim3(2*INNER/128, MTOK/128), 256>>>(
        h1, ipw, MTOK, 2*INNER, DD, nullptr, nullptr, EpBias{ipb, xz, 2*INNER});

    conv_silu_kernel<<<(MTOK*INNER)/256, 256>>>(xz, cw, cb, xm);

    gemm128<EpBiasSig><<<dim3(1, MTOK/128), 256>>>(
        xm, dtw, MTOK, SST, INNER, nullptr, nullptr, EpBiasSig{dtb, dt, SST});
    gemm128<EpBias><<<dim3(1, MTOK/128), 256>>>(
        xm, bpw, MTOK, SST, INNER, nullptr, nullptr, EpBias{bpb, Bm, SST});
    gemm128<EpBias><<<dim3(1, MTOK/128), 256>>>(
        xm, cpw, MTOK, SST, INNER, nullptr, nullptr, EpBias{cpb, Cm, SST});

    scan_kernel<<<1, 128>>>(dt, Bm, Cm, y);
    ln64_kernel<<<MTOK/4, 128>>>(y);

    gemm128<EpS2I><<<dim3(INNER/128, MTOK/128), 256>>>(
        y, s2iw, MTOK, INNER, SST, nullptr, nullptr, EpS2I{s2ib, Dp, xm, xz, u});

    gemm128<EpOut><<<dim3(DD/128, MTOK/128), 256>>>(
        u, ow, MTOK, DD, INNER, nullptr, nullptr, EpOut{obp, x, x2, out});

    // ---- MoE ----
    rmsnorm_kernel<<<MTOK, 256>>>(x2, n2w, h2);
    gate_kernel<<<MTOK/8, 256>>>(h2, gw, gb, wfull);
    build_lists_kernel<<<NE, 1024>>>(wfull, idx, wl, cnt);

    for (int e=0; e<NE; e++) {
        gemm128<EpGelu><<<dim3(HIDD/128, MTOK/128), 256>>>(
            h2, ew1 + (size_t)e*DD*HIDD, MTOK, HIDD, DD,
            cnt + e, idx + e*MTOK,
            EpGelu{eb1 + (size_t)e*HIDD, hid, HIDD});
        gemm128<EpMoE2><<<dim3(DD/128, MTOK/128), 256>>>(
            hid, ew2 + (size_t)e*HIDD*DD, MTOK, DD, HIDD,
            cnt + e, nullptr,
            EpMoE2{eb2 + (size_t)e*DD, idx + e*MTOK, wl + e*MTOK, out});
    }
}

// round 6
// speedup vs baseline: 2.0480x; 2.0480x over previous
#include <cuda_runtime.h>
#include <math.h>
#include <stdint.h>

// Problem constants
#define MTOK  4096      // B*T tokens
#define DD    1024      // model dim
#define INNER 2048      // expanded dim
#define SST   64        // state dim
#define HIDD  4096      // expert hidden
#define NE    4         // experts
#define TT    2048      // seq len
#define NB    2         // batch
#define NDBC  192       // fused dt|B|C output width

// ---------------- scratch (static device memory; no allocations) -------------
__device__ float g_h1 [(size_t)MTOK*DD];
__device__ float g_xz [(size_t)MTOK*2*INNER];
__device__ float g_xm [(size_t)MTOK*INNER];
__device__ float g_dt [(size_t)MTOK*SST];
__device__ float g_Bm [(size_t)MTOK*SST];
__device__ float g_Cm [(size_t)MTOK*SST];
__device__ float g_y  [(size_t)MTOK*SST];
__device__ float g_u  [(size_t)MTOK*INNER];
__device__ float g_x2 [(size_t)MTOK*DD];
__device__ float g_h2 [(size_t)MTOK*DD];
__device__ float g_hid[(size_t)MTOK*HIDD];
__device__ float g_wfull[(size_t)MTOK*NE];
__device__ float g_wdbc[(size_t)INNER*NDBC];
__device__ int   g_idx[NE*MTOK];
__device__ float g_wl [NE*MTOK];
__device__ int   g_cnt[NE];

__device__ __forceinline__ float sigmoidf_(float v){ return 1.0f/(1.0f+expf(-v)); }

// round-to-nearest tf32 conversion (explicit RNA; truncation would bias results)
__device__ __forceinline__ float tf32c(float x){
    uint32_t u; asm("cvt.rna.tf32.f32 %0, %1;" : "=r"(u) : "f"(x));
    return __uint_as_float(u);
}

__device__ __forceinline__ void mma_tf32(float4& d, const uint32_t* a, const uint32_t* b){
    asm volatile("mma.sync.aligned.m16n8k8.row.col.f32.tf32.tf32.f32 "
        "{%0,%1,%2,%3}, {%4,%5,%6,%7}, {%8,%9}, {%0,%1,%2,%3};"
        : "+f"(d.x), "+f"(d.y), "+f"(d.z), "+f"(d.w)
        : "r"(a[0]), "r"(a[1]), "r"(a[2]), "r"(a[3]), "r"(b[0]), "r"(b[1]));
}

// ---------------- epilogue functors ------------------------------------------
struct EpBias {
    const float* bias; float* C; int ldc;
    __device__ __forceinline__ void store(int r,int c,float acc) const {
        C[(size_t)r*ldc + c] = acc + bias[c];
    }
};
struct EpDBC {           // fused dt|Bm|Cm epilogue by column range
    const float *dtb,*bpb,*cpb; float *dt,*Bm,*Cm;
    __device__ __forceinline__ void store(int r,int c,float acc) const {
        if (c < 64)       dt[(size_t)r*SST + c]        = sigmoidf_(acc + dtb[c]);
        else if (c < 128) Bm[(size_t)r*SST + (c-64)]   = acc + bpb[c-64];
        else              Cm[(size_t)r*SST + (c-128)]  = acc + cpb[c-128];
    }
};
struct EpGelu {          // exact gelu, writes compacted hid rows
    const float* bias; float* C; int ldc;
    __device__ __forceinline__ void store(int r,int c,float acc) const {
        float v = acc + bias[c];
        C[(size_t)r*ldc + c] = 0.5f*v*(1.0f + erff(v*0.70710678118654752f));
    }
};
struct EpS2I {           // + s2i_b + D*x_main, * sigmoid(gate)
    const float* bias; const float* Dp; const float* xm; const float* xz; float* C;
    __device__ __forceinline__ void store(int r,int c,float acc) const {
        float v = acc + bias[c];
        v = fmaf(Dp[c], xm[(size_t)r*INNER + c], v);
        v *= sigmoidf_(xz[(size_t)r*(2*INNER) + INNER + c]);
        C[(size_t)r*INNER + c] = v;
    }
};
struct EpOut {           // + out_b + residual x ; dual store (x2 and d_out)
    const float* bias; const float* resid; float* C; float* out;
    __device__ __forceinline__ void store(int r,int c,float acc) const {
        float v = acc + bias[c] + resid[(size_t)r*DD + c];
        C[(size_t)r*DD + c] = v;
        out[(size_t)r*DD + c] = v;
    }
};
struct EpMoE2 {          // scatter: out[tok] += w * (acc + b2)
    const float* bias; const int* idx; const float* wl; float* out;
    __device__ __forceinline__ void store(int r,int c,float acc) const {
        int t = idx[r];
        out[(size_t)t*DD + c] += wl[r]*(acc + bias[c]);
    }
};

// ---------------- tf32 tensor-core GEMM: 128x128 tile, BK=16 -----------------
// A row-major [M,K] (optional row gather), B row-major [K,N]. fp32 accumulate.
// 8 warps in a 4(M) x 2(N) grid; warp tile 32x64 = 2 m16-tiles x 8 n8-tiles.
template<class Ep>
__global__ void __launch_bounds__(256)
gemm_tf32(const float* __restrict__ A, const float* __restrict__ B,
          int M, int N, int K,
          const int* __restrict__ mcnt,   // if non-null: device row count
          const int* __restrict__ ridx,   // if non-null: gather A rows
          Ep ep)
{
    constexpr int BM=128, BN=128, BK=16, LDP=136;   // 136: conflict-free frag LDS
    int Mr = mcnt ? *mcnt : M;
    int rb = blockIdx.y*BM;
    if (rb >= Mr) return;
    int nb = blockIdx.x*BN;

    __shared__ float As[BK][LDP];   // [k][m]
    __shared__ float Bs[BK][LDP];   // [k][n]

    int tid  = threadIdx.x;
    int lane = tid & 31, wid = tid >> 5;
    int wm = wid & 3, wn = wid >> 2;       // warp position
    int g  = lane >> 2, tg = lane & 3;     // groupID / thread-in-group

    float4 acc[2][8];
    #pragma unroll
    for (int i=0;i<2;i++)
        #pragma unroll
        for (int j=0;j<8;j++) acc[i][j] = make_float4(0.f,0.f,0.f,0.f);

    for (int k0=0; k0<K; k0+=BK) {
        // A tile: BM x BK, stored transposed As[k][m], converted to tf32
        #pragma unroll
        for (int i=0;i<2;i++) {
            int idv = tid*2 + i;            // 0..511
            int row = idv >> 2;             // 0..127
            int kq  = (idv & 3) * 4;        // 0,4,8,12
            float4 v = make_float4(0.f,0.f,0.f,0.f);
            int gr = rb + row;
            if (gr < Mr) {
                int ar = ridx ? ridx[gr] : gr;
                v = *reinterpret_cast<const float4*>(A + (size_t)ar*K + k0 + kq);
            }
            As[kq+0][row]=tf32c(v.x); As[kq+1][row]=tf32c(v.y);
            As[kq+2][row]=tf32c(v.z); As[kq+3][row]=tf32c(v.w);
        }
        // B tile: BK x BN, Bs[k][n], converted to tf32
        #pragma unroll
        for (int i=0;i<2;i++) {
            int idv = tid*2 + i;
            int kr = idv >> 5;              // 0..15
            int nq = (idv & 31) * 4;        // 0..124
            float4 v = make_float4(0.f,0.f,0.f,0.f);
            if (nb + nq < N)
                v = *reinterpret_cast<const float4*>(B + (size_t)(k0+kr)*N + nb + nq);
            v.x=tf32c(v.x); v.y=tf32c(v.y); v.z=tf32c(v.z); v.w=tf32c(v.w);
            *reinterpret_cast<float4*>(&Bs[kr][nq]) = v;
        }
        __syncthreads();

        #pragma unroll
        for (int ks=0; ks<BK; ks+=8) {
            uint32_t af[2][4];
            #pragma unroll
            for (int i=0;i<2;i++) {
                int m0 = wm*32 + i*16 + g;
                af[i][0] = __float_as_uint(As[ks+tg  ][m0  ]);
                af[i][1] = __float_as_uint(As[ks+tg  ][m0+8]);
                af[i][2] = __float_as_uint(As[ks+tg+4][m0  ]);
                af[i][3] = __float_as_uint(As[ks+tg+4][m0+8]);
            }
            uint32_t bf[8][2];
            #pragma unroll
            for (int j=0;j<8;j++) {
                int n0 = wn*64 + j*8 + g;
                bf[j][0] = __float_as_uint(Bs[ks+tg  ][n0]);
                bf[j][1] = __float_as_uint(Bs[ks+tg+4][n0]);
            }
            #pragma unroll
            for (int i=0;i<2;i++)
                #pragma unroll
                for (int j=0;j<8;j++) mma_tf32(acc[i][j], af[i], bf[j]);
        }
        __syncthreads();
    }

    #pragma unroll
    for (int i=0;i<2;i++) {
        int r0 = rb + wm*32 + i*16 + g;
        int r1 = r0 + 8;
        #pragma unroll
        for (int j=0;j<8;j++) {
            int c0 = nb + wn*64 + j*8 + tg*2;
            if (r0 < Mr) {
                if (c0   < N) ep.store(r0, c0,   acc[i][j].x);
                if (c0+1 < N) ep.store(r0, c0+1, acc[i][j].y);
            }
            if (r1 < Mr) {
                if (c0   < N) ep.store(r1, c0,   acc[i][j].z);
                if (c0+1 < N) ep.store(r1, c0+1, acc[i][j].w);
            }
        }
    }
}

// ---------------- concat dt|B|C weights into [INNER, 192] --------------------
__global__ void concat_dbc_kernel(const float* __restrict__ dtw,
                                  const float* __restrict__ bpw,
                                  const float* __restrict__ cpw,
                                  float* __restrict__ W)
{
    int i = blockIdx.x*blockDim.x + threadIdx.x;
    if (i >= INNER*NDBC) return;
    int r = i / NDBC, c = i % NDBC;
    float v;
    if (c < 64)       v = dtw[r*SST + c];
    else if (c < 128) v = bpw[r*SST + (c-64)];
    else              v = cpw[r*SST + (c-128)];
    W[i] = v;
}

// ---------------- rmsnorm (row of 1024), eps 1e-6 ----------------------------
__global__ void rmsnorm_kernel(const float* __restrict__ x, const float* __restrict__ w,
                               float* __restrict__ o)
{
    int r = blockIdx.x;
    const float* xr = x + (size_t)r*DD;
    float s = 0.f;
    for (int i=threadIdx.x; i<DD; i+=blockDim.x) { float v = xr[i]; s = fmaf(v,v,s); }
    #pragma unroll
    for (int off=16; off; off>>=1) s += __shfl_xor_sync(0xffffffffu, s, off);
    __shared__ float red[8];
    int wid = threadIdx.x>>5, lane = threadIdx.x&31;
    if (lane==0) red[wid]=s;
    __syncthreads();
    if (threadIdx.x==0) {
        float t=0.f;
        for (int i=0;i<(int)(blockDim.x>>5);i++) t += red[i];
        red[0] = rsqrtf(t/(float)DD + 1e-6f);
    }
    __syncthreads();
    float nr = red[0];
    float* orow = o + (size_t)r*DD;
    for (int i=threadIdx.x; i<DD; i+=blockDim.x) orow[i] = xr[i]*nr*w[i];
}

// ---------------- causal depthwise conv (K=3) + silu -------------------------
__global__ void conv_silu_kernel(const float* __restrict__ xz, const float* __restrict__ cw,
                                 const float* __restrict__ cb, float* __restrict__ xm)
{
    int idx = blockIdx.x*blockDim.x + threadIdx.x;       // over MTOK*INNER
    if (idx >= MTOK*INNER) return;
    int c   = idx & (INNER-1);
    int tok = idx >> 11;                                  // INNER = 2048
    int t   = tok & (TT-1);
    const float* base = xz + (size_t)tok*(2*INNER) + c;   // x_main half
    float v = cw[c*3+2]*base[0];
    if (t >= 1) v = fmaf(cw[c*3+1], base[-(ptrdiff_t)(2*INNER)],   v);
    if (t >= 2) v = fmaf(cw[c*3+0], base[-(ptrdiff_t)(4*INNER)],   v);
    v += cb[c];
    xm[idx] = v * sigmoidf_(v);
}

// ---------------- selective-state scan (serial over T) -----------------------
__global__ void scan_kernel(const float* __restrict__ dt, const float* __restrict__ Bv,
                            const float* __restrict__ Cv, float* __restrict__ y)
{
    int tid = threadIdx.x;          // 128 = NB * SST
    if (tid >= NB*SST) return;
    int b = tid >> 6, s = tid & 63;
    float st = 0.f;
    size_t off = ((size_t)b*TT)*SST + s;
    for (int t=0; t<TT; t++, off += SST) {
        float d = dt[off], bb = Bv[off], cc = Cv[off];
        st = fmaf(d, bb - st, st);           // (1-d)*st + d*b
        y[off] = cc*st;
    }
}

// ---------------- layernorm over 64 (one warp per token), eps 1e-5 -----------
__global__ void ln64_kernel(float* __restrict__ y)
{
    int gw = (blockIdx.x*blockDim.x + threadIdx.x) >> 5;
    if (gw >= MTOK) return;
    int lane = threadIdx.x & 31;
    float* r = y + (size_t)gw*SST;
    float v0 = r[lane], v1 = r[lane+32];
    float sum = v0 + v1;
    #pragma unroll
    for (int off=16; off; off>>=1) sum += __shfl_xor_sync(0xffffffffu, sum, off);
    float mu = sum * (1.0f/64.0f);
    float d0 = v0-mu, d1 = v1-mu;
    float vs = d0*d0 + d1*d1;
    #pragma unroll
    for (int off=16; off; off>>=1) vs += __shfl_xor_sync(0xffffffffu, vs, off);
    float nr = rsqrtf(vs*(1.0f/64.0f) + 1e-5f);
    r[lane]    = d0*nr;
    r[lane+32] = d1*nr;
}

// ---------------- gating: logits, top-2 softmax → dense weights --------------
__global__ void gate_kernel(const float* __restrict__ h2, const float* __restrict__ gw,
                            const float* __restrict__ gb, float* __restrict__ wfull)
{
    int gwarp = (blockIdx.x*blockDim.x + threadIdx.x) >> 5;
    if (gwarp >= MTOK) return;
    int lane = threadIdx.x & 31;
    float a0=0,a1=0,a2=0,a3=0;
    const float* hr = h2 + (size_t)gwarp*DD;
    for (int d=lane; d<DD; d+=32) {
        float h = hr[d];
        float4 w = *reinterpret_cast<const float4*>(gw + d*4);
        a0 = fmaf(h,w.x,a0); a1 = fmaf(h,w.y,a1);
        a2 = fmaf(h,w.z,a2); a3 = fmaf(h,w.w,a3);
    }
    #pragma unroll
    for (int off=16; off; off>>=1) {
        a0 += __shfl_xor_sync(0xffffffffu,a0,off);
        a1 += __shfl_xor_sync(0xffffffffu,a1,off);
        a2 += __shfl_xor_sync(0xffffffffu,a2,off);
        a3 += __shfl_xor_sync(0xffffffffu,a3,off);
    }
    if (lane==0) {
        float l[4] = {a0+gb[0], a1+gb[1], a2+gb[2], a3+gb[3]};
        int i0 = 0;
        for (int e=1;e<4;e++) if (l[e] > l[i0]) i0 = e;       // strict: earliest on tie
        int i1 = -1;
        for (int e=0;e<4;e++) if (e!=i0 && (i1<0 || l[e] > l[i1])) i1 = e;
        float e1 = expf(l[i1]-l[i0]);
        float p0 = 1.0f/(1.0f+e1);
        float p1 = e1/(1.0f+e1);
        float* wr = wfull + (size_t)gwarp*NE;
        wr[0]=0.f; wr[1]=0.f; wr[2]=0.f; wr[3]=0.f;
        wr[i0]=p0; wr[i1]=p1;
    }
}

// ---------------- deterministic per-expert token lists -----------------------
__global__ void build_lists_kernel(const float* __restrict__ wfull,
                                   int* __restrict__ idx, float* __restrict__ wl,
                                   int* __restrict__ cnt)
{
    int e = blockIdx.x;
    __shared__ int pref[1024];
    __shared__ int base;
    if (threadIdx.x==0) base = 0;
    __syncthreads();
    for (int chunk=0; chunk<MTOK/1024; chunk++) {
        int t = chunk*1024 + threadIdx.x;
        float w = wfull[(size_t)t*NE + e];
        int pred = (w > 0.f) ? 1 : 0;
        pref[threadIdx.x] = pred;
        __syncthreads();
        for (int off=1; off<1024; off<<=1) {
            int v = (threadIdx.x >= off) ? pref[threadIdx.x-off] : 0;
            __syncthreads();
            pref[threadIdx.x] += v;
            __syncthreads();
        }
        if (pred) {
            int pos = base + pref[threadIdx.x] - 1;
            idx[e*MTOK + pos] = t;
            wl [e*MTOK + pos] = w;
        }
        __syncthreads();
        if (threadIdx.x==0) base += pref[1023];
        __syncthreads();
    }
    if (threadIdx.x==0) cnt[e] = base;
}

// =============================================================================
extern "C" void kernel_launch(void* const* d_in, const int* in_sizes, int n_in,
                              void* d_out, int out_size)
{
    const float* x    = (const float*)d_in[0];
    const float* n1w  = (const float*)d_in[1];
    const float* n2w  = (const float*)d_in[2];
    const float* ipw  = (const float*)d_in[3];
    const float* ipb  = (const float*)d_in[4];
    const float* cw   = (const float*)d_in[5];
    const float* cb   = (const float*)d_in[6];
    const float* dtw  = (const float*)d_in[7];
    const float* dtb  = (const float*)d_in[8];
    const float* bpw  = (const float*)d_in[9];
    const float* bpb  = (const float*)d_in[10];
    const float* cpw  = (const float*)d_in[11];
    const float* cpb  = (const float*)d_in[12];
    const float* s2iw = (const float*)d_in[13];
    const float* s2ib = (const float*)d_in[14];
    const float* Dp   = (const float*)d_in[15];
    const float* ow   = (const float*)d_in[16];
    const float* obp  = (const float*)d_in[17];
    const float* gw   = (const float*)d_in[18];
    const float* gb   = (const float*)d_in[19];
    const float* ew1  = (const float*)d_in[20];
    const float* eb1  = (const float*)d_in[21];
    const float* ew2  = (const float*)d_in[22];
    const float* eb2  = (const float*)d_in[23];
    float* out = (float*)d_out;

    float *h1,*xz,*xm,*dt,*Bm,*Cm,*y,*u,*x2,*h2,*hid,*wfull,*wl,*wdbc;
    int *idx,*cnt;
    cudaGetSymbolAddress((void**)&h1,   g_h1);
    cudaGetSymbolAddress((void**)&xz,   g_xz);
    cudaGetSymbolAddress((void**)&xm,   g_xm);
    cudaGetSymbolAddress((void**)&dt,   g_dt);
    cudaGetSymbolAddress((void**)&Bm,   g_Bm);
    cudaGetSymbolAddress((void**)&Cm,   g_Cm);
    cudaGetSymbolAddress((void**)&y,    g_y);
    cudaGetSymbolAddress((void**)&u,    g_u);
    cudaGetSymbolAddress((void**)&x2,   g_x2);
    cudaGetSymbolAddress((void**)&h2,   g_h2);
    cudaGetSymbolAddress((void**)&hid,  g_hid);
    cudaGetSymbolAddress((void**)&wfull,g_wfull);
    cudaGetSymbolAddress((void**)&wl,   g_wl);
    cudaGetSymbolAddress((void**)&wdbc, g_wdbc);
    cudaGetSymbolAddress((void**)&idx,  g_idx);
    cudaGetSymbolAddress((void**)&cnt,  g_cnt);

    // ---- mixer ----
    rmsnorm_kernel<<<MTOK, 256>>>(x, n1w, h1);
    concat_dbc_kernel<<<(INNER*NDBC + 255)/256, 256>>>(dtw, bpw, cpw, wdbc);

    gemm_tf32<EpBias><<<dim3(2*INNER/128, MTOK/128), 256>>>(
        h1, ipw, MTOK, 2*INNER, DD, nullptr, nullptr, EpBias{ipb, xz, 2*INNER});

    conv_silu_kernel<<<(MTOK*INNER)/256, 256>>>(xz, cw, cb, xm);

    gemm_tf32<EpDBC><<<dim3(2, MTOK/128), 256>>>(
        xm, wdbc, MTOK, NDBC, INNER, nullptr, nullptr,
        EpDBC{dtb, bpb, cpb, dt, Bm, Cm});

    scan_kernel<<<1, 128>>>(dt, Bm, Cm, y);
    ln64_kernel<<<MTOK/4, 128>>>(y);

    gemm_tf32<EpS2I><<<dim3(INNER/128, MTOK/128), 256>>>(
        y, s2iw, MTOK, INNER, SST, nullptr, nullptr, EpS2I{s2ib, Dp, xm, xz, u});

    gemm_tf32<EpOut><<<dim3(DD/128, MTOK/128), 256>>>(
        u, ow, MTOK, DD, INNER, nullptr, nullptr, EpOut{obp, x, x2, out});

    // ---- MoE ----
    rmsnorm_kernel<<<MTOK, 256>>>(x2, n2w, h2);
    gate_kernel<<<MTOK/8, 256>>>(h2, gw, gb, wfull);
    build_lists_kernel<<<NE, 1024>>>(wfull, idx, wl, cnt);

    for (int e=0; e<NE; e++) {
        gemm_tf32<EpGelu><<<dim3(HIDD/128, MTOK/128), 256>>>(
            h2, ew1 + (size_t)e*DD*HIDD, MTOK, HIDD, DD,
            cnt + e, idx + e*MTOK,
            EpGelu{eb1 + (size_t)e*HIDD, hid, HIDD});
        gemm_tf32<EpMoE2><<<dim3(DD/128, MTOK/128), 256>>>(
            hid, ew2 + (size_t)e*HIDD*DD, MTOK, DD, HIDD,
            cnt + e, nullptr,
            EpMoE2{eb2 + (size_t)e*DD, idx + e*MTOK, wl + e*MTOK, out});
    }
}

// round 7
// speedup vs baseline: 3.0575x; 1.4929x over previous
#include <cuda_runtime.h>
#include <math.h>
#include <stdint.h>

// Problem constants
#define MTOK  4096      // B*T tokens
#define DD    1024      // model dim
#define INNER 2048      // expanded dim
#define SST   64        // state dim
#define HIDD  4096      // expert hidden
#define NE    4         // experts
#define TT    2048      // seq len
#define NB    2         // batch
#define NDBC  192       // fused dt|B|C output width

// ---------------- scratch (static device memory; no allocations) -------------
__device__ float g_h1 [(size_t)MTOK*DD];
__device__ float g_xz [(size_t)MTOK*2*INNER];
__device__ float g_xm [(size_t)MTOK*INNER];
__device__ float g_dt [(size_t)MTOK*SST];
__device__ float g_Bm [(size_t)MTOK*SST];
__device__ float g_Cm [(size_t)MTOK*SST];
__device__ float g_y  [(size_t)MTOK*SST];
__device__ float g_u  [(size_t)MTOK*INNER];
__device__ float g_x2 [(size_t)MTOK*DD];
__device__ float g_h2 [(size_t)MTOK*DD];
__device__ float g_hid[(size_t)MTOK*HIDD];
__device__ float g_wfull[(size_t)MTOK*NE];
__device__ float g_wdbc[(size_t)INNER*NDBC];
__device__ int   g_idx[NE*MTOK];
__device__ float g_wl [NE*MTOK];
__device__ int   g_cnt[NE];

__device__ __forceinline__ float sigmoidf_(float v){ return 1.0f/(1.0f+expf(-v)); }

// round-to-nearest tf32 conversion (explicit RNA; truncation would bias results)
__device__ __forceinline__ uint32_t tf32u(float x){
    uint32_t u; asm("cvt.rna.tf32.f32 %0, %1;" : "=r"(u) : "f"(x));
    return u;
}

__device__ __forceinline__ void mma_tf32(float4& d, const uint32_t* a, const uint32_t* b){
    asm volatile("mma.sync.aligned.m16n8k8.row.col.f32.tf32.tf32.f32 "
        "{%0,%1,%2,%3}, {%4,%5,%6,%7}, {%8,%9}, {%0,%1,%2,%3};"
        : "+f"(d.x), "+f"(d.y), "+f"(d.z), "+f"(d.w)
        : "r"(a[0]), "r"(a[1]), "r"(a[2]), "r"(a[3]), "r"(b[0]), "r"(b[1]));
}

// cp.async 16B with zero-fill when pred is false (src-size = 0)
__device__ __forceinline__ void cpa16(uint32_t dst, const void* src, bool pred){
    int sz = pred ? 16 : 0;
    asm volatile("cp.async.cg.shared.global [%0], [%1], 16, %2;\n"
                 :: "r"(dst), "l"(src), "r"(sz));
}
__device__ __forceinline__ void cpa_commit(){ asm volatile("cp.async.commit_group;\n"); }
__device__ __forceinline__ void cpa_wait1(){ asm volatile("cp.async.wait_group 1;\n"); }
__device__ __forceinline__ void cpa_wait0(){ asm volatile("cp.async.wait_group 0;\n"); }

// ---------------- epilogue functors ------------------------------------------
struct EpBias {
    const float* bias; float* C; int ldc;
    __device__ __forceinline__ void store(int r,int c,float acc) const {
        C[(size_t)r*ldc + c] = acc + bias[c];
    }
};
struct EpDBC {           // fused dt|Bm|Cm epilogue by column range
    const float *dtb,*bpb,*cpb; float *dt,*Bm,*Cm;
    __device__ __forceinline__ void store(int r,int c,float acc) const {
        if (c < 64)       dt[(size_t)r*SST + c]        = sigmoidf_(acc + dtb[c]);
        else if (c < 128) Bm[(size_t)r*SST + (c-64)]   = acc + bpb[c-64];
        else              Cm[(size_t)r*SST + (c-128)]  = acc + cpb[c-128];
    }
};
struct EpGelu {          // exact gelu, writes compacted hid rows
    const float* bias; float* C; int ldc;
    __device__ __forceinline__ void store(int r,int c,float acc) const {
        float v = acc + bias[c];
        C[(size_t)r*ldc + c] = 0.5f*v*(1.0f + erff(v*0.70710678118654752f));
    }
};
struct EpS2I {           // + s2i_b + D*x_main, * sigmoid(gate)
    const float* bias; const float* Dp; const float* xm; const float* xz; float* C;
    __device__ __forceinline__ void store(int r,int c,float acc) const {
        float v = acc + bias[c];
        v = fmaf(Dp[c], xm[(size_t)r*INNER + c], v);
        v *= sigmoidf_(xz[(size_t)r*(2*INNER) + INNER + c]);
        C[(size_t)r*INNER + c] = v;
    }
};
struct EpOut {           // + out_b + residual x ; dual store (x2 and d_out)
    const float* bias; const float* resid; float* C; float* out;
    __device__ __forceinline__ void store(int r,int c,float acc) const {
        float v = acc + bias[c] + resid[(size_t)r*DD + c];
        C[(size_t)r*DD + c] = v;
        out[(size_t)r*DD + c] = v;
    }
};
struct EpMoE2 {          // scatter: out[tok] += w * (acc + b2)
    const float* bias; const int* idx; const float* wl; float* out;
    __device__ __forceinline__ void store(int r,int c,float acc) const {
        int t = idx[r];
        out[(size_t)t*DD + c] += wl[r]*(acc + bias[c]);
    }
};

// ---------------- tf32 tensor-core GEMM, 2-stage cp.async pipeline -----------
// A row-major [M,K] (optional row gather), B row-major [K,N]. fp32 accumulate.
// 128x128 tile, BK=16. 8 warps in 4(M) x 2(N); warp tile 32x64.
// A staged [m][k] (LDA=20 pad), B staged [k][n] (LDB=136 pad): both layouts
// give conflict-free scalar fragment LDS.
template<class Ep>
__global__ void __launch_bounds__(256)
gemm_tf32(const float* __restrict__ A, const float* __restrict__ B,
          int M, int N, int K,
          const int* __restrict__ mcnt,   // if non-null: device row count
          const int* __restrict__ ridx,   // if non-null: gather A rows
          Ep ep)
{
    constexpr int BM=128, BN=128, BK=16;
    constexpr int LDA=20, LDB=136;
    int Mr = mcnt ? *mcnt : M;
    int rb = blockIdx.y*BM;
    if (rb >= Mr) return;
    int nb = blockIdx.x*BN;

    __shared__ float As[2][BM][LDA];   // 2*128*20*4  = 20480 B
    __shared__ float Bs[2][BK][LDB];   // 2*16*136*4  = 17408 B

    int tid  = threadIdx.x;
    int lane = tid & 31, wid = tid >> 5;
    int wm = wid & 3, wn = wid >> 2;
    int g  = lane >> 2, tg = lane & 3;

    // ---- per-thread load descriptors (fixed across k-tiles) ----
    // A: thread covers one row, two 16B chunks (kq and kq+4..)
    int a_row = tid >> 1;                     // 0..127
    int a_kq0 = (tid & 1) ? 8 : 0;            // chunks at kq0, kq0+4
    bool a_ok = (rb + a_row) < Mr;
    const float* a_src = nullptr;
    if (a_ok) {
        int ar = ridx ? ridx[rb + a_row] : (rb + a_row);
        a_src = A + (size_t)ar*K + a_kq0;
    }
    uint32_t a_dst0 = (uint32_t)__cvta_generic_to_shared(&As[0][a_row][a_kq0]);
    uint32_t a_dst1 = (uint32_t)__cvta_generic_to_shared(&As[1][a_row][a_kq0]);

    // B: thread covers two 16B chunks
    int b_kr0 = (2*tid)     >> 5;             // row of chunk 0
    int b_nq0 = ((2*tid)    & 31) * 4;
    int b_kr1 = (2*tid + 1) >> 5;
    int b_nq1 = ((2*tid + 1)& 31) * 4;
    bool b_ok0 = (nb + b_nq0) < N;
    bool b_ok1 = (nb + b_nq1) < N;
    const float* b_src0 = B + (size_t)b_kr0*N + nb + b_nq0;
    const float* b_src1 = B + (size_t)b_kr1*N + nb + b_nq1;
    uint32_t b_dst0[2] = {
        (uint32_t)__cvta_generic_to_shared(&Bs[0][b_kr0][b_nq0]),
        (uint32_t)__cvta_generic_to_shared(&Bs[1][b_kr0][b_nq0]) };
    uint32_t b_dst1[2] = {
        (uint32_t)__cvta_generic_to_shared(&Bs[0][b_kr1][b_nq1]),
        (uint32_t)__cvta_generic_to_shared(&Bs[1][b_kr1][b_nq1]) };

    float4 acc[2][8];
    #pragma unroll
    for (int i=0;i<2;i++)
        #pragma unroll
        for (int j=0;j<8;j++) acc[i][j] = make_float4(0.f,0.f,0.f,0.f);

    int KT = K/BK;

    // prologue: load tile 0 into stage 0
    {
        cpa16(a_dst0,      a_src,                 a_ok);
        cpa16(a_dst0 + 16, a_src ? a_src+4 : A,   a_ok);
        cpa16(b_dst0[0], b_src0, b_ok0);
        cpa16(b_dst1[0], b_src1, b_ok1);
        cpa_commit();
    }

    for (int kt=0; kt<KT; kt++) {
        int s = kt & 1;
        // issue next tile's loads into the other stage
        if (kt+1 < KT) {
            int ns = (kt+1) & 1;
            const float* as = a_src ? a_src + (size_t)(kt+1)*BK : nullptr;
            uint32_t ad = ns ? a_dst1 : a_dst0;
            cpa16(ad,      as,               a_ok);
            cpa16(ad + 16, as ? as+4 : A,    a_ok);
            size_t boff = (size_t)(kt+1)*BK*N;
            cpa16(b_dst0[ns], b_src0 + boff, b_ok0);
            cpa16(b_dst1[ns], b_src1 + boff, b_ok1);
        }
        cpa_commit();
        cpa_wait1();          // tile kt resident; tile kt+1 may be in flight
        __syncthreads();

        #pragma unroll
        for (int ks=0; ks<BK; ks+=8) {
            uint32_t af[2][4];
            #pragma unroll
            for (int i=0;i<2;i++) {
                int m0 = wm*32 + i*16 + g;
                af[i][0] = tf32u(As[s][m0  ][ks+tg  ]);
                af[i][1] = tf32u(As[s][m0+8][ks+tg  ]);
                af[i][2] = tf32u(As[s][m0  ][ks+tg+4]);
                af[i][3] = tf32u(As[s][m0+8][ks+tg+4]);
            }
            uint32_t bf[8][2];
            #pragma unroll
            for (int j=0;j<8;j++) {
                int n0 = wn*64 + j*8 + g;
                bf[j][0] = tf32u(Bs[s][ks+tg  ][n0]);
                bf[j][1] = tf32u(Bs[s][ks+tg+4][n0]);
            }
            #pragma unroll
            for (int i=0;i<2;i++)
                #pragma unroll
                for (int j=0;j<8;j++) mma_tf32(acc[i][j], af[i], bf[j]);
        }
        __syncthreads();
    }

    #pragma unroll
    for (int i=0;i<2;i++) {
        int r0 = rb + wm*32 + i*16 + g;
        int r1 = r0 + 8;
        #pragma unroll
        for (int j=0;j<8;j++) {
            int c0 = nb + wn*64 + j*8 + tg*2;
            if (r0 < Mr) {
                if (c0   < N) ep.store(r0, c0,   acc[i][j].x);
                if (c0+1 < N) ep.store(r0, c0+1, acc[i][j].y);
            }
            if (r1 < Mr) {
                if (c0   < N) ep.store(r1, c0,   acc[i][j].z);
                if (c0+1 < N) ep.store(r1, c0+1, acc[i][j].w);
            }
        }
    }
}

// ---------------- concat dt|B|C weights into [INNER, 192] --------------------
__global__ void concat_dbc_kernel(const float* __restrict__ dtw,
                                  const float* __restrict__ bpw,
                                  const float* __restrict__ cpw,
                                  float* __restrict__ W)
{
    int i = blockIdx.x*blockDim.x + threadIdx.x;
    if (i >= INNER*NDBC) return;
    int r = i / NDBC, c = i % NDBC;
    float v;
    if (c < 64)       v = dtw[r*SST + c];
    else if (c < 128) v = bpw[r*SST + (c-64)];
    else              v = cpw[r*SST + (c-128)];
    W[i] = v;
}

// ---------------- rmsnorm (row of 1024), eps 1e-6 ----------------------------
__global__ void rmsnorm_kernel(const float* __restrict__ x, const float* __restrict__ w,
                               float* __restrict__ o)
{
    int r = blockIdx.x;
    const float* xr = x + (size_t)r*DD;
    float s = 0.f;
    for (int i=threadIdx.x; i<DD; i+=blockDim.x) { float v = xr[i]; s = fmaf(v,v,s); }
    #pragma unroll
    for (int off=16; off; off>>=1) s += __shfl_xor_sync(0xffffffffu, s, off);
    __shared__ float red[8];
    int wid = threadIdx.x>>5, lane = threadIdx.x&31;
    if (lane==0) red[wid]=s;
    __syncthreads();
    if (threadIdx.x==0) {
        float t=0.f;
        for (int i=0;i<(int)(blockDim.x>>5);i++) t += red[i];
        red[0] = rsqrtf(t/(float)DD + 1e-6f);
    }
    __syncthreads();
    float nr = red[0];
    float* orow = o + (size_t)r*DD;
    for (int i=threadIdx.x; i<DD; i+=blockDim.x) orow[i] = xr[i]*nr*w[i];
}

// ---------------- causal depthwise conv (K=3) + silu -------------------------
__global__ void conv_silu_kernel(const float* __restrict__ xz, const float* __restrict__ cw,
                                 const float* __restrict__ cb, float* __restrict__ xm)
{
    int idx = blockIdx.x*blockDim.x + threadIdx.x;       // over MTOK*INNER
    if (idx >= MTOK*INNER) return;
    int c   = idx & (INNER-1);
    int tok = idx >> 11;                                  // INNER = 2048
    int t   = tok & (TT-1);
    const float* base = xz + (size_t)tok*(2*INNER) + c;   // x_main half
    float v = cw[c*3+2]*base[0];
    if (t >= 1) v = fmaf(cw[c*3+1], base[-(ptrdiff_t)(2*INNER)],   v);
    if (t >= 2) v = fmaf(cw[c*3+0], base[-(ptrdiff_t)(4*INNER)],   v);
    v += cb[c];
    xm[idx] = v * sigmoidf_(v);
}

// ---------------- selective-state scan (serial over T) -----------------------
__global__ void scan_kernel(const float* __restrict__ dt, const float* __restrict__ Bv,
                            const float* __restrict__ Cv, float* __restrict__ y)
{
    int tid = threadIdx.x;          // 128 = NB * SST
    if (tid >= NB*SST) return;
    int b = tid >> 6, s = tid & 63;
    float st = 0.f;
    size_t off = ((size_t)b*TT)*SST + s;
    for (int t=0; t<TT; t++, off += SST) {
        float d = dt[off], bb = Bv[off], cc = Cv[off];
        st = fmaf(d, bb - st, st);           // (1-d)*st + d*b
        y[off] = cc*st;
    }
}

// ---------------- layernorm over 64 (one warp per token), eps 1e-5 -----------
__global__ void ln64_kernel(float* __restrict__ y)
{
    int gw = (blockIdx.x*blockDim.x + threadIdx.x) >> 5;
    if (gw >= MTOK) return;
    int lane = threadIdx.x & 31;
    float* r = y + (size_t)gw*SST;
    float v0 = r[lane], v1 = r[lane+32];
    float sum = v0 + v1;
    #pragma unroll
    for (int off=16; off; off>>=1) sum += __shfl_xor_sync(0xffffffffu, sum, off);
    float mu = sum * (1.0f/64.0f);
    float d0 = v0-mu, d1 = v1-mu;
    float vs = d0*d0 + d1*d1;
    #pragma unroll
    for (int off=16; off; off>>=1) vs += __shfl_xor_sync(0xffffffffu, vs, off);
    float nr = rsqrtf(vs*(1.0f/64.0f) + 1e-5f);
    r[lane]    = d0*nr;
    r[lane+32] = d1*nr;
}

// ---------------- gating: logits, top-2 softmax → dense weights --------------
__global__ void gate_kernel(const float* __restrict__ h2, const float* __restrict__ gw,
                            const float* __restrict__ gb, float* __restrict__ wfull)
{
    int gwarp = (blockIdx.x*blockDim.x + threadIdx.x) >> 5;
    if (gwarp >= MTOK) return;
    int lane = threadIdx.x & 31;
    float a0=0,a1=0,a2=0,a3=0;
    const float* hr = h2 + (size_t)gwarp*DD;
    for (int d=lane; d<DD; d+=32) {
        float h = hr[d];
        float4 w = *reinterpret_cast<const float4*>(gw + d*4);
        a0 = fmaf(h,w.x,a0); a1 = fmaf(h,w.y,a1);
        a2 = fmaf(h,w.z,a2); a3 = fmaf(h,w.w,a3);
    }
    #pragma unroll
    for (int off=16; off; off>>=1) {
        a0 += __shfl_xor_sync(0xffffffffu,a0,off);
        a1 += __shfl_xor_sync(0xffffffffu,a1,off);
        a2 += __shfl_xor_sync(0xffffffffu,a2,off);
        a3 += __shfl_xor_sync(0xffffffffu,a3,off);
    }
    if (lane==0) {
        float l[4] = {a0+gb[0], a1+gb[1], a2+gb[2], a3+gb[3]};
        int i0 = 0;
        for (int e=1;e<4;e++) if (l[e] > l[i0]) i0 = e;       // strict: earliest on tie
        int i1 = -1;
        for (int e=0;e<4;e++) if (e!=i0 && (i1<0 || l[e] > l[i1])) i1 = e;
        float e1 = expf(l[i1]-l[i0]);
        float p0 = 1.0f/(1.0f+e1);
        float p1 = e1/(1.0f+e1);
        float* wr = wfull + (size_t)gwarp*NE;
        wr[0]=0.f; wr[1]=0.f; wr[2]=0.f; wr[3]=0.f;
        wr[i0]=p0; wr[i1]=p1;
    }
}

// ---------------- deterministic per-expert token lists -----------------------
__global__ void build_lists_kernel(const float* __restrict__ wfull,
                                   int* __restrict__ idx, float* __restrict__ wl,
                                   int* __restrict__ cnt)
{
    int e = blockIdx.x;
    __shared__ int pref[1024];
    __shared__ int base;
    if (threadIdx.x==0) base = 0;
    __syncthreads();
    for (int chunk=0; chunk<MTOK/1024; chunk++) {
        int t = chunk*1024 + threadIdx.x;
        float w = wfull[(size_t)t*NE + e];
        int pred = (w > 0.f) ? 1 : 0;
        pref[threadIdx.x] = pred;
        __syncthreads();
        for (int off=1; off<1024; off<<=1) {
            int v = (threadIdx.x >= off) ? pref[threadIdx.x-off] : 0;
            __syncthreads();
            pref[threadIdx.x] += v;
            __syncthreads();
        }
        if (pred) {
            int pos = base + pref[threadIdx.x] - 1;
            idx[e*MTOK + pos] = t;
            wl [e*MTOK + pos] = w;
        }
        __syncthreads();
        if (threadIdx.x==0) base += pref[1023];
        __syncthreads();
    }
    if (threadIdx.x==0) cnt[e] = base;
}

// =============================================================================
extern "C" void kernel_launch(void* const* d_in, const int* in_sizes, int n_in,
                              void* d_out, int out_size)
{
    const float* x    = (const float*)d_in[0];
    const float* n1w  = (const float*)d_in[1];
    const float* n2w  = (const float*)d_in[2];
    const float* ipw  = (const float*)d_in[3];
    const float* ipb  = (const float*)d_in[4];
    const float* cw   = (const float*)d_in[5];
    const float* cb   = (const float*)d_in[6];
    const float* dtw  = (const float*)d_in[7];
    const float* dtb  = (const float*)d_in[8];
    const float* bpw  = (const float*)d_in[9];
    const float* bpb  = (const float*)d_in[10];
    const float* cpw  = (const float*)d_in[11];
    const float* cpb  = (const float*)d_in[12];
    const float* s2iw = (const float*)d_in[13];
    const float* s2ib = (const float*)d_in[14];
    const float* Dp   = (const float*)d_in[15];
    const float* ow   = (const float*)d_in[16];
    const float* obp  = (const float*)d_in[17];
    const float* gw   = (const float*)d_in[18];
    const float* gb   = (const float*)d_in[19];
    const float* ew1  = (const float*)d_in[20];
    const float* eb1  = (const float*)d_in[21];
    const float* ew2  = (const float*)d_in[22];
    const float* eb2  = (const float*)d_in[23];
    float* out = (float*)d_out;

    float *h1,*xz,*xm,*dt,*Bm,*Cm,*y,*u,*x2,*h2,*hid,*wfull,*wl,*wdbc;
    int *idx,*cnt;
    cudaGetSymbolAddress((void**)&h1,   g_h1);
    cudaGetSymbolAddress((void**)&xz,   g_xz);
    cudaGetSymbolAddress((void**)&xm,   g_xm);
    cudaGetSymbolAddress((void**)&dt,   g_dt);
    cudaGetSymbolAddress((void**)&Bm,   g_Bm);
    cudaGetSymbolAddress((void**)&Cm,   g_Cm);
    cudaGetSymbolAddress((void**)&y,    g_y);
    cudaGetSymbolAddress((void**)&u,    g_u);
    cudaGetSymbolAddress((void**)&x2,   g_x2);
    cudaGetSymbolAddress((void**)&h2,   g_h2);
    cudaGetSymbolAddress((void**)&hid,  g_hid);
    cudaGetSymbolAddress((void**)&wfull,g_wfull);
    cudaGetSymbolAddress((void**)&wl,   g_wl);
    cudaGetSymbolAddress((void**)&wdbc, g_wdbc);
    cudaGetSymbolAddress((void**)&idx,  g_idx);
    cudaGetSymbolAddress((void**)&cnt,  g_cnt);

    // ---- mixer ----
    rmsnorm_kernel<<<MTOK, 256>>>(x, n1w, h1);
    concat_dbc_kernel<<<(INNER*NDBC + 255)/256, 256>>>(dtw, bpw, cpw, wdbc);

    gemm_tf32<EpBias><<<dim3(2*INNER/128, MTOK/128), 256>>>(
        h1, ipw, MTOK, 2*INNER, DD, nullptr, nullptr, EpBias{ipb, xz, 2*INNER});

    conv_silu_kernel<<<(MTOK*INNER)/256, 256>>>(xz, cw, cb, xm);

    gemm_tf32<EpDBC><<<dim3(2, MTOK/128), 256>>>(
        xm, wdbc, MTOK, NDBC, INNER, nullptr, nullptr,
        EpDBC{dtb, bpb, cpb, dt, Bm, Cm});

    scan_kernel<<<1, 128>>>(dt, Bm, Cm, y);
    ln64_kernel<<<MTOK/4, 128>>>(y);

    gemm_tf32<EpS2I><<<dim3(INNER/128, MTOK/128), 256>>>(
        y, s2iw, MTOK, INNER, SST, nullptr, nullptr, EpS2I{s2ib, Dp, xm, xz, u});

    gemm_tf32<EpOut><<<dim3(DD/128, MTOK/128), 256>>>(
        u, ow, MTOK, DD, INNER, nullptr, nullptr, EpOut{obp, x, x2, out});

    // ---- MoE ----
    rmsnorm_kernel<<<MTOK, 256>>>(x2, n2w, h2);
    gate_kernel<<<MTOK/8, 256>>>(h2, gw, gb, wfull);
    build_lists_kernel<<<NE, 1024>>>(wfull, idx, wl, cnt);

    for (int e=0; e<NE; e++) {
        gemm_tf32<EpGelu><<<dim3(HIDD/128, MTOK/128), 256>>>(
            h2, ew1 + (size_t)e*DD*HIDD, MTOK, HIDD, DD,
            cnt + e, idx + e*MTOK,
            EpGelu{eb1 + (size_t)e*HIDD, hid, HIDD});
        gemm_tf32<EpMoE2><<<dim3(DD/128, MTOK/128), 256>>>(
            hid, ew2 + (size_t)e*HIDD*DD, MTOK, DD, HIDD,
            cnt + e, nullptr,
            EpMoE2{eb2 + (size_t)e*DD, idx + e*MTOK, wl + e*MTOK, out});
    }
}